// round 4
// baseline (speedup 1.0000x reference)
#include <cuda_runtime.h>
#include <cstdint>

// Problem constants
#define T_STEPS 8192
#define D_INP   512
#define HDIM    768      // H
#define G3      2304     // 3*H
#define RTOT    4608     // 2 dirs * 3H
#define DH2     1536     // 2*H
#define NCTA    128      // persistent CTAs in the sequential pass
#define NWARP   12       // GRU units per CTA (one warp each); 128*12 = 1536 units

// ---------------- scratch (device globals; no allocation allowed) -------------
__device__ float  g_Gi0[(size_t)T_STEPS * RTOT];       // W_ih0 @ x + b_ih0   [T,4608]
__device__ float  g_Gi1[(size_t)T_STEPS * RTOT];       // W_ih1 @ h0seq + b   [T,4608]
__device__ float2 g_H0f[(size_t)(T_STEPS + 1) * DH2];  // layer0 hidden (value, flag)
__device__ float2 g_H1f[(size_t)(T_STEPS + 1) * DH2];  // layer1 hidden (value, flag)
__device__ float  g_H0p[(size_t)(T_STEPS + 1) * DH2];  // plain copy of layer0 hidden (GEMM input)

// ---------------- volatile 8B load/store helpers ------------------------------
__device__ __forceinline__ float2 ldvol2(const float2* p) {
    float2 v;
    asm volatile("ld.volatile.global.v2.f32 {%0,%1},[%2];"
                 : "=f"(v.x), "=f"(v.y) : "l"(p));
    return v;
}
__device__ __forceinline__ void stvol2(float2* p, float x, float y) {
    asm volatile("st.volatile.global.v2.f32 [%0],{%1,%2};"
                 :: "l"(p), "f"(x), "f"(y) : "memory");
}

// ---------------- clear flags for rows 1..T of both hidden buffers ------------
__global__ void clear_kernel() {
    size_t n = (size_t)T_STEPS * DH2;              // float2 elements per buffer (rows 1..T)
    float4* a = reinterpret_cast<float4*>(g_H0f + DH2);   // 2 float2 = 1 float4
    float4* b = reinterpret_cast<float4*>(g_H1f + DH2);
    size_t n4 = n / 2;
    float4 z = make_float4(0.f, 0.f, 0.f, 0.f);
    for (size_t i = (size_t)blockIdx.x * blockDim.x + threadIdx.x;
         i < n4; i += (size_t)gridDim.x * blockDim.x) {
        a[i] = z;
        b[i] = z;
    }
}

// ---------------- init: seed hidden state row 0 -------------------------------
__global__ void init_kernel(const float* __restrict__ h0) {
    int j = blockIdx.x * blockDim.x + threadIdx.x;
    if (j < DH2) {
        // torch layout h0[L*2, H]; layer0 dirs = rows 0,1 ; layer1 dirs = rows 2,3
        g_H0f[j] = make_float2(h0[j], 1.0f);
        g_H1f[j] = make_float2(h0[DH2 + j], 1.0f);
        g_H0p[j] = h0[j];
    }
}

// ---------------- SGEMM (NT): C[t][m] = sum_k A[t][k] * B[m][k] + bias[m] -----
// A: [T, K] row-major (lda = K), B: [RTOT, K] row-major, C: [T, RTOT]
// 128x128 tile, BK=16, 256 threads, 8x8 per-thread microtile.
__global__ __launch_bounds__(256) void sgemm_nt(
    const float* __restrict__ A, const float* __restrict__ B,
    const float* __restrict__ bias, int K, int which)
{
    float* C = which ? g_Gi1 : g_Gi0;
    const float* Ab;
    if (A == nullptr) Ab = g_H0p + DH2 + (size_t)blockIdx.y * 128 * K;  // layer-1 input seq
    else              Ab = A + (size_t)blockIdx.y * 128 * K;

    __shared__ float As[16][128];
    __shared__ float Bs[16][128];
    const int tid = threadIdx.x;
    const int tx = tid & 15;        // N (rows of W)
    const int ty = tid >> 4;        // M (timesteps)
    const float* Bb = B + (size_t)blockIdx.x * 128 * K;

    float acc[8][8];
#pragma unroll
    for (int i = 0; i < 8; i++)
#pragma unroll
        for (int j = 0; j < 8; j++) acc[i][j] = 0.f;

    for (int k0 = 0; k0 < K; k0 += 16) {
#pragma unroll
        for (int q = 0; q < 2; q++) {
            int f   = tid * 2 + q;          // 0..511 float4 slots
            int row = f >> 2;
            int c4  = (f & 3) * 4;
            float4 va = *reinterpret_cast<const float4*>(Ab + (size_t)row * K + k0 + c4);
            As[c4 + 0][row] = va.x; As[c4 + 1][row] = va.y;
            As[c4 + 2][row] = va.z; As[c4 + 3][row] = va.w;
            float4 vb = *reinterpret_cast<const float4*>(Bb + (size_t)row * K + k0 + c4);
            Bs[c4 + 0][row] = vb.x; Bs[c4 + 1][row] = vb.y;
            Bs[c4 + 2][row] = vb.z; Bs[c4 + 3][row] = vb.w;
        }
        __syncthreads();
#pragma unroll
        for (int kk = 0; kk < 16; kk++) {
            float4 a0 = *reinterpret_cast<const float4*>(&As[kk][ty * 8]);
            float4 a1 = *reinterpret_cast<const float4*>(&As[kk][ty * 8 + 4]);
            float4 b0 = *reinterpret_cast<const float4*>(&Bs[kk][tx * 8]);
            float4 b1 = *reinterpret_cast<const float4*>(&Bs[kk][tx * 8 + 4]);
            float ra[8] = {a0.x, a0.y, a0.z, a0.w, a1.x, a1.y, a1.z, a1.w};
            float rb[8] = {b0.x, b0.y, b0.z, b0.w, b1.x, b1.y, b1.z, b1.w};
#pragma unroll
            for (int i = 0; i < 8; i++)
#pragma unroll
                for (int j = 0; j < 8; j++)
                    acc[i][j] += ra[i] * rb[j];
        }
        __syncthreads();
    }
    const int cb = blockIdx.x * 128 + tx * 8;
    float bb[8];
#pragma unroll
    for (int j = 0; j < 8; j++) bb[j] = bias[cb + j];
#pragma unroll
    for (int i = 0; i < 8; i++) {
        float* Cp = C + (size_t)(blockIdx.y * 128 + ty * 8 + i) * RTOT + cb;
#pragma unroll
        for (int j = 0; j < 8; j++) Cp[j] = acc[i][j] + bb[j];
    }
}

// ---------------- sequential GRU pass: barrier-free dataflow ------------------
// One warp per GRU unit (dir d, hidden index i). w_hh rows live in registers
// (24 fp32 per gate per lane). Hidden state transported as (value, flag) float2
// pairs; each warp polls exactly the 24 words it needs and free-runs. No
// atomics, no grid barrier, no __syncthreads.
__global__ __launch_bounds__(NWARP * 32) void gru_pass(
    const float* __restrict__ Whh,   // [2, 3H, H] flat
    const float* __restrict__ bhh,   // [2, 3H] flat
    int layer)
{
    const float* Gi = layer ? g_Gi1 : g_Gi0;
    float2* Hf = layer ? g_H1f : g_H0f;

    const int warp = threadIdx.x >> 5;
    const int lane = threadIdx.x & 31;
    const int u = blockIdx.x * NWARP + warp;   // 0..1535
    const int d = u / HDIM;
    const int i = u % HDIM;

    // Load this unit's w_hh rows (r,z,n) into registers, strided by lane.
    float wr[24], wz[24], wn[24];
    const float* base = Whh + (size_t)d * G3 * HDIM;
#pragma unroll
    for (int m = 0; m < 24; m++) {
        int k = lane + 32 * m;
        wr[m] = base[(size_t)(i) * HDIM + k];
        wz[m] = base[(size_t)(HDIM + i) * HDIM + k];
        wn[m] = base[(size_t)(2 * HDIM + i) * HDIM + k];
    }
    const float br = bhh[d * G3 + i];
    const float bz = bhh[d * G3 + HDIM + i];
    const float bn = bhh[d * G3 + 2 * HDIM + i];

    // Unit's own previous hidden value, kept in a register (lane 0 only uses it).
    float hprev = ldvol2(&Hf[u]).x;

    for (int t = 0; t < T_STEPS; t++) {
        // Issue precomputed input-gate loads first so DRAM latency hides under poll.
        float gr = 0.f, gz = 0.f, gn = 0.f;
        if (lane == 0) {
            const float* gp = Gi + (size_t)t * RTOT + d * G3 + i;
            gr = __ldg(gp);
            gz = __ldg(gp + HDIM);
            gn = __ldg(gp + 2 * HDIM);
        }

        // Poll-load the 24 (value, flag) pairs this lane needs from step t's row.
        const float2* hrow = Hf + (size_t)t * DH2 + d * HDIM;
        float hv[24];
        unsigned pend = 0x00FFFFFFu;
        while (true) {
#pragma unroll
            for (int m = 0; m < 24; m++) {
                if (pend & (1u << m)) {
                    float2 p = ldvol2(hrow + lane + 32 * m);
                    if (p.y != 0.f) { hv[m] = p.x; pend &= ~(1u << m); }
                }
            }
            if (!__any_sync(0xffffffffu, pend != 0u)) break;
        }

        float ar = 0.f, az = 0.f, an = 0.f;
#pragma unroll
        for (int m = 0; m < 24; m++) {
            ar += wr[m] * hv[m];
            az += wz[m] * hv[m];
            an += wn[m] * hv[m];
        }
#pragma unroll
        for (int off = 16; off > 0; off >>= 1) {
            ar += __shfl_down_sync(0xffffffffu, ar, off);
            az += __shfl_down_sync(0xffffffffu, az, off);
            an += __shfl_down_sync(0xffffffffu, an, off);
        }
        if (lane == 0) {
            float r = 1.f / (1.f + __expf(-(gr + ar + br)));
            float z = 1.f / (1.f + __expf(-(gz + az + bz)));
            float n = tanhf(gn + r * (an + bn));
            float hnew = (1.f - z) * n + z * hprev;
            hprev = hnew;
            // Single 8B store carries data + readiness flag atomically.
            stvol2(&Hf[(size_t)(t + 1) * DH2 + u], hnew, 1.0f);
            if (layer == 0)
                g_H0p[(size_t)(t + 1) * DH2 + u] = hnew;  // plain copy for the Gi1 GEMM
        }
    }
}

// ---------------- final FC + sigmoid ------------------------------------------
__global__ void fc_kernel(const float* __restrict__ fcw,
                          const float* __restrict__ fcb,
                          float* __restrict__ out)
{
    int gw = (blockIdx.x * blockDim.x + threadIdx.x) >> 5;   // output index
    int lane = threadIdx.x & 31;
    if (gw >= 256) return;
    const float2* h = g_H1f + (size_t)T_STEPS * DH2;
    float acc = 0.f;
    for (int k = lane; k < DH2; k += 32)
        acc += fcw[(size_t)gw * DH2 + k] * h[k].x;
#pragma unroll
    for (int off = 16; off > 0; off >>= 1)
        acc += __shfl_down_sync(0xffffffffu, acc, off);
    if (lane == 0)
        out[gw] = 1.f / (1.f + __expf(-(acc + fcb[gw])));
}

// ---------------- launch ------------------------------------------------------
extern "C" void kernel_launch(void* const* d_in, const int* in_sizes, int n_in,
                              void* d_out, int out_size)
{
    const float* x     = (const float*)d_in[0];
    const float* h0    = (const float*)d_in[1];
    const float* w_ih0 = (const float*)d_in[2];
    const float* w_hh0 = (const float*)d_in[3];
    const float* b_ih0 = (const float*)d_in[4];
    const float* b_hh0 = (const float*)d_in[5];
    const float* w_ih1 = (const float*)d_in[6];
    const float* w_hh1 = (const float*)d_in[7];
    const float* b_ih1 = (const float*)d_in[8];
    const float* b_hh1 = (const float*)d_in[9];
    const float* fc_w  = (const float*)d_in[10];
    const float* fc_b  = (const float*)d_in[11];
    float* out = (float*)d_out;

    (void)in_sizes; (void)n_in; (void)out_size;

    // Reset readiness flags (rows 1..T of both hidden buffers), then seed row 0.
    clear_kernel<<<2048, 256>>>();
    init_kernel<<<6, 256>>>(h0);

    // Gi0 = W_ih0 @ x + b_ih0
    sgemm_nt<<<dim3(RTOT / 128, T_STEPS / 128), 256>>>(x, w_ih0, b_ih0, D_INP, 0);

    // layer 0 sequential pass (barrier-free dataflow)
    gru_pass<<<NCTA, NWARP * 32>>>(w_hh0, b_hh0, 0);

    // Gi1 = W_ih1 @ h0_seq + b_ih1  (A=nullptr -> kernel uses g_H0p+DH2)
    sgemm_nt<<<dim3(RTOT / 128, T_STEPS / 128), 256>>>(nullptr, w_ih1, b_ih1, DH2, 1);

    // layer 1 sequential pass
    gru_pass<<<NCTA, NWARP * 32>>>(w_hh1, b_hh1, 1);

    // final FC + sigmoid
    fc_kernel<<<32, 256>>>(fc_w, fc_b, out);
}

// round 6
// speedup vs baseline: 1.1550x; 1.1550x over previous
#include <cuda_runtime.h>
#include <cstdint>

// Problem constants
#define T_STEPS 8192
#define D_INP   512
#define HDIM    768      // H
#define G3      2304     // 3*H
#define RTOT    4608     // 2 dirs * 3H
#define DH2     1536     // 2*H
#define NCTA    128      // persistent CTAs in the sequential pass
#define NWARP   12       // GRU units per CTA (one warp each); 128*12 = 1536 units
#define NTHR    (NWARP * 32)

// ---------------- scratch (device globals; no allocation allowed) -------------
__device__ float g_Gi0[(size_t)T_STEPS * RTOT];        // W_ih0 @ x + b_ih0   [T,4608]
__device__ float g_Gi1[(size_t)T_STEPS * RTOT];        // W_ih1 @ h0seq + b   [T,4608]
__device__ float g_H0[(size_t)(T_STEPS + 1) * DH2];    // layer0 hidden seq (row 0 = init)
__device__ float g_H1[(size_t)(T_STEPS + 1) * DH2];    // layer1 hidden seq
__device__ unsigned g_slots[2][NCTA];                  // barrier slots per layer

// ---------------- packed f32x2 fma (Blackwell; PTX-only) ----------------------
__device__ __forceinline__ unsigned long long fma2(unsigned long long a,
                                                   unsigned long long b,
                                                   unsigned long long c) {
    unsigned long long d;
    asm("fma.rn.f32x2 %0,%1,%2,%3;" : "=l"(d) : "l"(a), "l"(b), "l"(c));
    return d;
}
__device__ __forceinline__ float f2sum(unsigned long long v) {
    float2 f = *reinterpret_cast<float2*>(&v);
    return f.x + f.y;
}

// ---------------- init: seed hidden state row 0, zero barrier slots -----------
__global__ void init_kernel(const float* __restrict__ h0) {
    int j = blockIdx.x * blockDim.x + threadIdx.x;
    if (j < DH2) {
        // torch layout h0[L*2, H]; layer0 dirs = rows 0,1 ; layer1 dirs = rows 2,3
        g_H0[j] = h0[j];
        g_H1[j] = h0[DH2 + j];
    }
    if (j < 2 * NCTA) g_slots[j / NCTA][j % NCTA] = 0u;
}

// ---------------- SGEMM (NT): C[t][m] = sum_k A[t][k] * B[m][k] + bias[m] -----
// A: [T, K] row-major (lda = K), B: [RTOT, K] row-major, C: [T, RTOT]
// 128x128 tile, BK=16, 256 threads, 8x8 per-thread microtile.
__global__ __launch_bounds__(256) void sgemm_nt(
    const float* __restrict__ A, const float* __restrict__ B,
    const float* __restrict__ bias, int K, int which)
{
    float* C = which ? g_Gi1 : g_Gi0;
    const float* Ab;
    if (A == nullptr) Ab = g_H0 + DH2 + (size_t)blockIdx.y * 128 * K;   // layer-1 input seq
    else              Ab = A + (size_t)blockIdx.y * 128 * K;

    __shared__ float As[16][128];
    __shared__ float Bs[16][128];
    const int tid = threadIdx.x;
    const int tx = tid & 15;        // N (rows of W)
    const int ty = tid >> 4;        // M (timesteps)
    const float* Bb = B + (size_t)blockIdx.x * 128 * K;

    float acc[8][8];
#pragma unroll
    for (int i = 0; i < 8; i++)
#pragma unroll
        for (int j = 0; j < 8; j++) acc[i][j] = 0.f;

    for (int k0 = 0; k0 < K; k0 += 16) {
#pragma unroll
        for (int q = 0; q < 2; q++) {
            int f   = tid * 2 + q;          // 0..511 float4 slots
            int row = f >> 2;
            int c4  = (f & 3) * 4;
            float4 va = *reinterpret_cast<const float4*>(Ab + (size_t)row * K + k0 + c4);
            As[c4 + 0][row] = va.x; As[c4 + 1][row] = va.y;
            As[c4 + 2][row] = va.z; As[c4 + 3][row] = va.w;
            float4 vb = *reinterpret_cast<const float4*>(Bb + (size_t)row * K + k0 + c4);
            Bs[c4 + 0][row] = vb.x; Bs[c4 + 1][row] = vb.y;
            Bs[c4 + 2][row] = vb.z; Bs[c4 + 3][row] = vb.w;
        }
        __syncthreads();
#pragma unroll
        for (int kk = 0; kk < 16; kk++) {
            float4 a0 = *reinterpret_cast<const float4*>(&As[kk][ty * 8]);
            float4 a1 = *reinterpret_cast<const float4*>(&As[kk][ty * 8 + 4]);
            float4 b0 = *reinterpret_cast<const float4*>(&Bs[kk][tx * 8]);
            float4 b1 = *reinterpret_cast<const float4*>(&Bs[kk][tx * 8 + 4]);
            float ra[8] = {a0.x, a0.y, a0.z, a0.w, a1.x, a1.y, a1.z, a1.w};
            float rb[8] = {b0.x, b0.y, b0.z, b0.w, b1.x, b1.y, b1.z, b1.w};
#pragma unroll
            for (int i = 0; i < 8; i++)
#pragma unroll
                for (int j = 0; j < 8; j++)
                    acc[i][j] += ra[i] * rb[j];
        }
        __syncthreads();
    }
    const int cb = blockIdx.x * 128 + tx * 8;
    float bb[8];
#pragma unroll
    for (int j = 0; j < 8; j++) bb[j] = bias[cb + j];
#pragma unroll
    for (int i = 0; i < 8; i++) {
        float* Cp = C + (size_t)(blockIdx.y * 128 + ty * 8 + i) * RTOT + cb;
#pragma unroll
        for (int j = 0; j < 8; j++) Cp[j] = acc[i][j] + bb[j];
    }
}

// ---------------- sequential GRU pass (persistent, flat slot barrier) ---------
// One warp per GRU unit (dir d, hidden index i). w_hh rows register-resident as
// packed f32x2 (36 b64 regs/lane). Per step: packed matvec from shared h, warp
// reduce, gate math on lane 0, store 1 float, slot barrier (no atomics), reload
// h row via L2.
__global__ __launch_bounds__(NTHR) void gru_pass(
    const float* __restrict__ Whh,   // [2, 3H, H] flat
    const float* __restrict__ bhh,   // [2, 3H] flat
    int layer)
{
    const float* Gi = layer ? g_Gi1 : g_Gi0;
    float* Hs = layer ? g_H1 : g_H0;
    unsigned* slots = g_slots[layer];

    __shared__ float h_sh[DH2];
    const int warp = threadIdx.x >> 5;
    const int lane = threadIdx.x & 31;
    const int u = blockIdx.x * NWARP + warp;   // 0..1535
    const int d = u / HDIM;
    const int i = u % HDIM;

    // Load this unit's w_hh rows (r,z,n) into registers as packed f32x2.
    // Lane handles pairs p = lane + 32*m  (k = 2p, 2p+1), m = 0..11.
    unsigned long long wr[12], wz[12], wn[12];
    {
        const float* base = Whh + (size_t)d * G3 * HDIM;
        const unsigned long long* r64 = reinterpret_cast<const unsigned long long*>(base + (size_t)i * HDIM);
        const unsigned long long* z64 = reinterpret_cast<const unsigned long long*>(base + (size_t)(HDIM + i) * HDIM);
        const unsigned long long* n64 = reinterpret_cast<const unsigned long long*>(base + (size_t)(2 * HDIM + i) * HDIM);
#pragma unroll
        for (int m = 0; m < 12; m++) {
            int p = lane + 32 * m;
            wr[m] = r64[p]; wz[m] = z64[p]; wn[m] = n64[p];
        }
    }
    const float br = bhh[d * G3 + i];
    const float bz = bhh[d * G3 + HDIM + i];
    const float bn = bhh[d * G3 + 2 * HDIM + i];

    // Preload h row 0 (seeded by init_kernel). 384 threads x float4 = 1536 floats.
    reinterpret_cast<float4*>(h_sh)[threadIdx.x] =
        __ldcg(reinterpret_cast<const float4*>(Hs) + threadIdx.x);
    __syncthreads();

    for (int t = 0; t < T_STEPS; t++) {
        // Input-side gates: issue early (DRAM latency hides under compute+barrier).
        float gr = 0.f, gz = 0.f, gn = 0.f;
        if (lane == 0) {
            const float* gp = Gi + (size_t)t * RTOT + d * G3 + i;
            gr = __ldg(gp);
            gz = __ldg(gp + HDIM);
            gn = __ldg(gp + 2 * HDIM);
        }

        // Packed h2h matvec.
        const unsigned long long* h64 =
            reinterpret_cast<const unsigned long long*>(h_sh + d * HDIM);
        unsigned long long ar = 0ull, az = 0ull, an = 0ull;
#pragma unroll
        for (int m = 0; m < 12; m++) {
            unsigned long long hv = h64[lane + 32 * m];
            ar = fma2(wr[m], hv, ar);
            az = fma2(wz[m], hv, az);
            an = fma2(wn[m], hv, an);
        }
        float sr = f2sum(ar), sz = f2sum(az), sn = f2sum(an);
#pragma unroll
        for (int off = 16; off > 0; off >>= 1) {
            sr += __shfl_down_sync(0xffffffffu, sr, off);
            sz += __shfl_down_sync(0xffffffffu, sz, off);
            sn += __shfl_down_sync(0xffffffffu, sn, off);
        }

        if (lane == 0) {
            float r = 1.f / (1.f + __expf(-(gr + sr + br)));
            float z = 1.f / (1.f + __expf(-(gz + sz + bz)));
            float n = tanhf(gn + r * (sn + bn));
            float hprev = h_sh[d * HDIM + i];
            float hnew = (1.f - z) * n + z * hprev;
            __stcg(&Hs[(size_t)(t + 1) * DH2 + u], hnew);
            __threadfence();
        }
        __syncthreads();

        // ---- flat slot barrier (no atomics) ----
        if (warp == 0) {
            unsigned tgt = (unsigned)(t + 1);
            if (lane == 0)
                asm volatile("st.volatile.global.u32 [%0],%1;"
                             :: "l"(slots + blockIdx.x), "r"(tgt) : "memory");
            const uint4* sp4 = reinterpret_cast<const uint4*>(slots);
            while (true) {
                uint4 v;
                asm volatile("ld.volatile.global.v4.u32 {%0,%1,%2,%3},[%4];"
                             : "=r"(v.x), "=r"(v.y), "=r"(v.z), "=r"(v.w)
                             : "l"(sp4 + lane));
                bool ok = (v.x >= tgt) & (v.y >= tgt) & (v.z >= tgt) & (v.w >= tgt);
                if (__all_sync(0xffffffffu, ok)) break;
            }
        }
        __syncthreads();

        // Reload h row t+1 through L2.
        reinterpret_cast<float4*>(h_sh)[threadIdx.x] =
            __ldcg(reinterpret_cast<const float4*>(Hs + (size_t)(t + 1) * DH2) + threadIdx.x);
        __syncthreads();
    }
}

// ---------------- final FC + sigmoid ------------------------------------------
__global__ void fc_kernel(const float* __restrict__ fcw,
                          const float* __restrict__ fcb,
                          float* __restrict__ out)
{
    int gw = (blockIdx.x * blockDim.x + threadIdx.x) >> 5;   // output index
    int lane = threadIdx.x & 31;
    if (gw >= 256) return;
    const float* h = g_H1 + (size_t)T_STEPS * DH2;
    float acc = 0.f;
    for (int k = lane; k < DH2; k += 32)
        acc += fcw[(size_t)gw * DH2 + k] * h[k];
#pragma unroll
    for (int off = 16; off > 0; off >>= 1)
        acc += __shfl_down_sync(0xffffffffu, acc, off);
    if (lane == 0)
        out[gw] = 1.f / (1.f + __expf(-(acc + fcb[gw])));
}

// ---------------- launch ------------------------------------------------------
extern "C" void kernel_launch(void* const* d_in, const int* in_sizes, int n_in,
                              void* d_out, int out_size)
{
    const float* x     = (const float*)d_in[0];
    const float* h0    = (const float*)d_in[1];
    const float* w_ih0 = (const float*)d_in[2];
    const float* w_hh0 = (const float*)d_in[3];
    const float* b_ih0 = (const float*)d_in[4];
    const float* b_hh0 = (const float*)d_in[5];
    const float* w_ih1 = (const float*)d_in[6];
    const float* w_hh1 = (const float*)d_in[7];
    const float* b_ih1 = (const float*)d_in[8];
    const float* b_hh1 = (const float*)d_in[9];
    const float* fc_w  = (const float*)d_in[10];
    const float* fc_b  = (const float*)d_in[11];
    float* out = (float*)d_out;

    (void)in_sizes; (void)n_in; (void)out_size;

    init_kernel<<<6, 256>>>(h0);

    // Gi0 = W_ih0 @ x + b_ih0
    sgemm_nt<<<dim3(RTOT / 128, T_STEPS / 128), 256>>>(x, w_ih0, b_ih0, D_INP, 0);

    // layer 0 sequential pass
    gru_pass<<<NCTA, NTHR>>>(w_hh0, b_hh0, 0);

    // Gi1 = W_ih1 @ h0_seq + b_ih1  (A=nullptr -> kernel uses g_H0+DH2)
    sgemm_nt<<<dim3(RTOT / 128, T_STEPS / 128), 256>>>(nullptr, w_ih1, b_ih1, DH2, 1);

    // layer 1 sequential pass
    gru_pass<<<NCTA, NTHR>>>(w_hh1, b_hh1, 1);

    // final FC + sigmoid
    fc_kernel<<<32, 256>>>(fc_w, fc_b, out);
}

// round 7
// speedup vs baseline: 2.6657x; 2.3079x over previous
#include <cuda_runtime.h>
#include <cstdint>

// Problem constants
#define T_STEPS 8192
#define D_INP   512
#define HDIM    768      // H
#define G3      2304     // 3*H
#define RTOT    4608     // 2 dirs * 3H
#define DH2     1536     // 2*H
#define NCTA    128      // persistent CTAs total (64 per direction)
#define GCTA    64       // CTAs per direction group
#define NWARP   12       // GRU units per CTA; 64*12 = 768 = H units per direction
#define NTHR    (NWARP * 32)

// ---------------- scratch (device globals; no allocation allowed) -------------
__device__ float g_Gi0[(size_t)T_STEPS * RTOT];        // W_ih0 @ x + b_ih0   [T,4608]
__device__ float g_Gi1[(size_t)T_STEPS * RTOT];        // W_ih1 @ h0seq + b   [T,4608]
__device__ float g_H0[(size_t)(T_STEPS + 1) * DH2];    // layer0 hidden seq (row 0 = init)
__device__ float g_H1[(size_t)(T_STEPS + 1) * DH2];    // layer1 hidden seq
__device__ unsigned g_cnt[2][2];                       // [layer][dir] arrival counters

// ---------------- packed f32x2 helpers (Blackwell; PTX-only) ------------------
__device__ __forceinline__ unsigned long long fma2(unsigned long long a,
                                                   unsigned long long b,
                                                   unsigned long long c) {
    unsigned long long d;
    asm("fma.rn.f32x2 %0,%1,%2,%3;" : "=l"(d) : "l"(a), "l"(b), "l"(c));
    return d;
}
__device__ __forceinline__ unsigned long long pack2(float x, float y) {
    unsigned long long r;
    asm("mov.b64 %0,{%1,%2};" : "=l"(r) : "f"(x), "f"(y));
    return r;
}
__device__ __forceinline__ float2 unpack2(unsigned long long v) {
    float2 f;
    asm("mov.b64 {%0,%1},%2;" : "=f"(f.x), "=f"(f.y) : "l"(v));
    return f;
}

// ---------------- init: seed hidden state row 0, zero counters ----------------
__global__ void init_kernel(const float* __restrict__ h0) {
    int j = blockIdx.x * blockDim.x + threadIdx.x;
    if (j < DH2) {
        // torch layout h0[L*2, H]; layer0 dirs = rows 0,1 ; layer1 dirs = rows 2,3
        g_H0[j] = h0[j];
        g_H1[j] = h0[DH2 + j];
    }
    if (j < 4) g_cnt[j >> 1][j & 1] = 0u;
}

// ---------------- SGEMM (NT) with packed f32x2 FMA ----------------------------
// C[t][m] = sum_k A[t][k] * B[m][k] + bias[m]
// A: [T, K] row-major, B: [RTOT, K] row-major, C: [T, RTOT]
// 128x128 tile, BK=16, 256 threads, 8x8 per-thread microtile (as 8x4 f32x2).
__global__ __launch_bounds__(256) void sgemm_nt(
    const float* __restrict__ A, const float* __restrict__ B,
    const float* __restrict__ bias, int K, int which)
{
    float* C = which ? g_Gi1 : g_Gi0;
    const float* Ab;
    if (A == nullptr) Ab = g_H0 + DH2 + (size_t)blockIdx.y * 128 * K;   // layer-1 input seq
    else              Ab = A + (size_t)blockIdx.y * 128 * K;

    __shared__ float As[16][128];
    __shared__ float Bs[16][128];
    const int tid = threadIdx.x;
    const int tx = tid & 15;        // N (rows of W)
    const int ty = tid >> 4;        // M (timesteps)
    const float* Bb = B + (size_t)blockIdx.x * 128 * K;

    unsigned long long acc2[8][4];
#pragma unroll
    for (int i = 0; i < 8; i++)
#pragma unroll
        for (int j = 0; j < 4; j++) acc2[i][j] = 0ull;

    for (int k0 = 0; k0 < K; k0 += 16) {
#pragma unroll
        for (int q = 0; q < 2; q++) {
            int f   = tid * 2 + q;          // 0..511 float4 slots
            int row = f >> 2;
            int c4  = (f & 3) * 4;
            float4 va = *reinterpret_cast<const float4*>(Ab + (size_t)row * K + k0 + c4);
            As[c4 + 0][row] = va.x; As[c4 + 1][row] = va.y;
            As[c4 + 2][row] = va.z; As[c4 + 3][row] = va.w;
            float4 vb = *reinterpret_cast<const float4*>(Bb + (size_t)row * K + k0 + c4);
            Bs[c4 + 0][row] = vb.x; Bs[c4 + 1][row] = vb.y;
            Bs[c4 + 2][row] = vb.z; Bs[c4 + 3][row] = vb.w;
        }
        __syncthreads();
#pragma unroll
        for (int kk = 0; kk < 16; kk++) {
            float4 a0 = *reinterpret_cast<const float4*>(&As[kk][ty * 8]);
            float4 a1 = *reinterpret_cast<const float4*>(&As[kk][ty * 8 + 4]);
            float4 b0 = *reinterpret_cast<const float4*>(&Bs[kk][tx * 8]);
            float4 b1 = *reinterpret_cast<const float4*>(&Bs[kk][tx * 8 + 4]);
            unsigned long long rb2[4] = {pack2(b0.x, b0.y), pack2(b0.z, b0.w),
                                         pack2(b1.x, b1.y), pack2(b1.z, b1.w)};
            float ra[8] = {a0.x, a0.y, a0.z, a0.w, a1.x, a1.y, a1.z, a1.w};
#pragma unroll
            for (int i = 0; i < 8; i++) {
                unsigned long long ra2 = pack2(ra[i], ra[i]);
#pragma unroll
                for (int j = 0; j < 4; j++)
                    acc2[i][j] = fma2(ra2, rb2[j], acc2[i][j]);
            }
        }
        __syncthreads();
    }
    const int cb = blockIdx.x * 128 + tx * 8;
    float bb[8];
#pragma unroll
    for (int j = 0; j < 8; j++) bb[j] = bias[cb + j];
#pragma unroll
    for (int i = 0; i < 8; i++) {
        float* Cp = C + (size_t)(blockIdx.y * 128 + ty * 8 + i) * RTOT + cb;
#pragma unroll
        for (int j = 0; j < 4; j++) {
            float2 f = unpack2(acc2[i][j]);
            Cp[2 * j]     = f.x + bb[2 * j];
            Cp[2 * j + 1] = f.y + bb[2 * j + 1];
        }
    }
}

// ---------------- sequential GRU pass (direction-split, REDG barrier) ---------
// 128 CTAs: even CTAs = dir 0, odd CTAs = dir 1; each group of 64 CTAs syncs
// only among itself (the two directions are independent). One warp per GRU
// unit; w_hh register-resident as packed f32x2. Barrier: red.relaxed arrival
// on a monotone counter + ld.acquire poll on the SAME counter (no epoch flag,
// no atomic-with-return serialization).
__global__ __launch_bounds__(NTHR) void gru_pass(
    const float* __restrict__ Whh,   // [2, 3H, H] flat
    const float* __restrict__ bhh,   // [2, 3H] flat
    int layer)
{
    const float* Gi = layer ? g_Gi1 : g_Gi0;
    float* Hs = layer ? g_H1 : g_H0;

    const int d = blockIdx.x & 1;            // direction
    const int g = blockIdx.x >> 1;           // group-local CTA id (0..63)
    unsigned* cnt = &g_cnt[layer][d];

    __shared__ float h_sh[HDIM];             // own direction's hidden vector
    const int warp = threadIdx.x >> 5;
    const int lane = threadIdx.x & 31;
    const int i = g * NWARP + warp;          // 0..767 (hidden index within dir)
    const int u = d * HDIM + i;              // global unit index

    // Load this unit's w_hh rows (r,z,n) into registers as packed f32x2.
    unsigned long long wr[12], wz[12], wn[12];
    {
        const float* base = Whh + (size_t)d * G3 * HDIM;
        const unsigned long long* r64 = reinterpret_cast<const unsigned long long*>(base + (size_t)i * HDIM);
        const unsigned long long* z64 = reinterpret_cast<const unsigned long long*>(base + (size_t)(HDIM + i) * HDIM);
        const unsigned long long* n64 = reinterpret_cast<const unsigned long long*>(base + (size_t)(2 * HDIM + i) * HDIM);
#pragma unroll
        for (int m = 0; m < 12; m++) {
            int p = lane + 32 * m;
            wr[m] = r64[p]; wz[m] = z64[p]; wn[m] = n64[p];
        }
    }
    const float br = bhh[d * G3 + i];
    const float bz = bhh[d * G3 + HDIM + i];
    const float bn = bhh[d * G3 + 2 * HDIM + i];

    // Stage h row 0 (seeded by init_kernel; kernel-boundary sync makes it visible).
    {
        const float2* src = reinterpret_cast<const float2*>(Hs + d * HDIM);
        reinterpret_cast<float2*>(h_sh)[threadIdx.x] = __ldcg(src + threadIdx.x);
    }
    __syncthreads();

    float hprev = h_sh[i];                   // only lane 0's copy is used

    // Prefetch Gi gates for step 0.
    float gr = 0.f, gz = 0.f, gn = 0.f;
    if (lane == 0) {
        const float* gp = Gi + d * G3 + i;
        gr = __ldg(gp); gz = __ldg(gp + HDIM); gn = __ldg(gp + 2 * HDIM);
    }

    for (int t = 0; t < T_STEPS; t++) {
        // Packed h2h matvec from shared memory.
        const unsigned long long* h64 = reinterpret_cast<const unsigned long long*>(h_sh);
        unsigned long long ar = 0ull, az = 0ull, an = 0ull;
#pragma unroll
        for (int m = 0; m < 12; m++) {
            unsigned long long hv = h64[lane + 32 * m];
            ar = fma2(wr[m], hv, ar);
            az = fma2(wz[m], hv, az);
            an = fma2(wn[m], hv, an);
        }
        float2 fr = unpack2(ar), fz = unpack2(az), fn = unpack2(an);
        float sr = fr.x + fr.y, sz = fz.x + fz.y, sn = fn.x + fn.y;
#pragma unroll
        for (int off = 16; off > 0; off >>= 1) {
            sr += __shfl_down_sync(0xffffffffu, sr, off);
            sz += __shfl_down_sync(0xffffffffu, sz, off);
            sn += __shfl_down_sync(0xffffffffu, sn, off);
        }

        // Prefetch next step's Gi gates (~full step of latency to cover DRAM).
        float gr_n = 0.f, gz_n = 0.f, gn_n = 0.f;
        if (lane == 0 && t + 1 < T_STEPS) {
            const float* gp = Gi + (size_t)(t + 1) * RTOT + d * G3 + i;
            gr_n = __ldg(gp); gz_n = __ldg(gp + HDIM); gn_n = __ldg(gp + 2 * HDIM);
        }

        if (lane == 0) {
            float r = 1.f / (1.f + __expf(-(gr + sr + br)));
            float z = 1.f / (1.f + __expf(-(gz + sz + bz)));
            float n = tanhf(gn + r * (sn + bn));
            float hnew = (1.f - z) * n + z * hprev;
            hprev = hnew;
            __stcg(&Hs[(size_t)(t + 1) * DH2 + u], hnew);
        }
        gr = gr_n; gz = gz_n; gn = gn_n;

        __syncthreads();                       // all 12 warps' h stores issued
        if (threadIdx.x == 0) {
            __threadfence();                   // publish CTA's stores
            asm volatile("red.relaxed.gpu.global.add.u32 [%0],1;"
                         :: "l"(cnt) : "memory");
        }

        // Poll the monotone counter (all lanes load same word -> 1 req/warp).
        unsigned tgt = (unsigned)(t + 1) * GCTA;
        unsigned v;
        do {
            asm volatile("ld.acquire.gpu.global.u32 %0,[%1];" : "=r"(v) : "l"(cnt));
        } while (v < tgt);

        // Stage h row t+1 (own direction only: 3 KB).
        const float2* src = reinterpret_cast<const float2*>(Hs + (size_t)(t + 1) * DH2 + d * HDIM);
        reinterpret_cast<float2*>(h_sh)[threadIdx.x] = __ldcg(src + threadIdx.x);
        __syncthreads();
    }
}

// ---------------- final FC + sigmoid ------------------------------------------
__global__ void fc_kernel(const float* __restrict__ fcw,
                          const float* __restrict__ fcb,
                          float* __restrict__ out)
{
    int gw = (blockIdx.x * blockDim.x + threadIdx.x) >> 5;   // output index
    int lane = threadIdx.x & 31;
    if (gw >= 256) return;
    const float* h = g_H1 + (size_t)T_STEPS * DH2;
    float acc = 0.f;
    for (int k = lane; k < DH2; k += 32)
        acc += fcw[(size_t)gw * DH2 + k] * h[k];
#pragma unroll
    for (int off = 16; off > 0; off >>= 1)
        acc += __shfl_down_sync(0xffffffffu, acc, off);
    if (lane == 0)
        out[gw] = 1.f / (1.f + __expf(-(acc + fcb[gw])));
}

// ---------------- launch ------------------------------------------------------
extern "C" void kernel_launch(void* const* d_in, const int* in_sizes, int n_in,
                              void* d_out, int out_size)
{
    const float* x     = (const float*)d_in[0];
    const float* h0    = (const float*)d_in[1];
    const float* w_ih0 = (const float*)d_in[2];
    const float* w_hh0 = (const float*)d_in[3];
    const float* b_ih0 = (const float*)d_in[4];
    const float* b_hh0 = (const float*)d_in[5];
    const float* w_ih1 = (const float*)d_in[6];
    const float* w_hh1 = (const float*)d_in[7];
    const float* b_ih1 = (const float*)d_in[8];
    const float* b_hh1 = (const float*)d_in[9];
    const float* fc_w  = (const float*)d_in[10];
    const float* fc_b  = (const float*)d_in[11];
    float* out = (float*)d_out;

    (void)in_sizes; (void)n_in; (void)out_size;

    init_kernel<<<6, 256>>>(h0);

    // Gi0 = W_ih0 @ x + b_ih0
    sgemm_nt<<<dim3(RTOT / 128, T_STEPS / 128), 256>>>(x, w_ih0, b_ih0, D_INP, 0);

    // layer 0 sequential pass
    gru_pass<<<NCTA, NTHR>>>(w_hh0, b_hh0, 0);

    // Gi1 = W_ih1 @ h0_seq + b_ih1  (A=nullptr -> kernel uses g_H0+DH2)
    sgemm_nt<<<dim3(RTOT / 128, T_STEPS / 128), 256>>>(nullptr, w_ih1, b_ih1, DH2, 1);

    // layer 1 sequential pass
    gru_pass<<<NCTA, NTHR>>>(w_hh1, b_hh1, 1);

    // final FC + sigmoid
    fc_kernel<<<32, 256>>>(fc_w, fc_b, out);
}

// round 9
// speedup vs baseline: 3.6596x; 1.3728x over previous
#include <cuda_runtime.h>
#include <cstdint>

// Problem constants
#define T_STEPS 8192
#define D_INP   512
#define HDIM    768      // H
#define G3      2304     // 3*H
#define RTOT    4608     // 2 dirs * 3H
#define DH2     1536     // 2*H
#define NCTA    128      // persistent CTAs total (64 per direction)
#define GCTA    64       // CTAs per direction group
#define NWARP   12       // GRU units per CTA; 64*12 = 768 = H units per direction
#define NTHR    (NWARP * 32)

// ---------------- scratch (device globals; no allocation allowed) -------------
__device__ float g_Gi0[(size_t)T_STEPS * RTOT];        // W_ih0 @ x + b_ih0   [T,4608]
__device__ float g_Gi1[(size_t)T_STEPS * RTOT];        // W_ih1 @ h0seq + b   [T,4608]
__device__ float g_H0[(size_t)(T_STEPS + 1) * DH2];    // layer0 hidden seq (row 0 = init)
__device__ float g_H1[(size_t)(T_STEPS + 1) * DH2];    // layer1 hidden seq
__device__ unsigned g_cnt[2][2];                       // [layer][dir] arrival counters

// ---------------- packed f32x2 helpers (Blackwell; PTX-only) ------------------
__device__ __forceinline__ unsigned long long fma2(unsigned long long a,
                                                   unsigned long long b,
                                                   unsigned long long c) {
    unsigned long long d;
    asm("fma.rn.f32x2 %0,%1,%2,%3;" : "=l"(d) : "l"(a), "l"(b), "l"(c));
    return d;
}
__device__ __forceinline__ unsigned long long pack2(float x, float y) {
    unsigned long long r;
    asm("mov.b64 %0,{%1,%2};" : "=l"(r) : "f"(x), "f"(y));
    return r;
}
__device__ __forceinline__ float2 unpack2(unsigned long long v) {
    float2 f;
    asm("mov.b64 {%0,%1},%2;" : "=f"(f.x), "=f"(f.y) : "l"(v));
    return f;
}

// ---------------- init: seed hidden state row 0, zero counters ----------------
__global__ void init_kernel(const float* __restrict__ h0) {
    int j = blockIdx.x * blockDim.x + threadIdx.x;
    if (j < DH2) {
        // torch layout h0[L*2, H]; layer0 dirs = rows 0,1 ; layer1 dirs = rows 2,3
        g_H0[j] = h0[j];
        g_H1[j] = h0[DH2 + j];
    }
    if (j < 4) g_cnt[j >> 1][j & 1] = 0u;
}

// ---------------- SGEMM (NT), double-buffered smem pipeline -------------------
// C[t][m] = sum_k A[t][k] * B[m][k] + bias[m]
// A: [T, K] row-major, B: [RTOT, K] row-major, C: [T, RTOT]
// 128x128 tile, BK=16, 256 threads, 8x8 microtile via packed f32x2 FMA.
__global__ __launch_bounds__(256) void sgemm_nt(
    const float* __restrict__ A, const float* __restrict__ B,
    const float* __restrict__ bias, int K, int which)
{
    float* C = which ? g_Gi1 : g_Gi0;
    const float* Ab;
    if (A == nullptr) Ab = g_H0 + DH2 + (size_t)blockIdx.y * 128 * K;   // layer-1 input seq
    else              Ab = A + (size_t)blockIdx.y * 128 * K;

    __shared__ float As[2][16][128];
    __shared__ float Bs[2][16][128];
    const int tid = threadIdx.x;
    const int tx = tid & 15;        // N (rows of W)
    const int ty = tid >> 4;        // M (timesteps)
    const float* Bb = B + (size_t)blockIdx.x * 128 * K;

    // Per-thread staging slots: f = tid*2+q -> row = f>>2, col4 = (f&3)*4
    const int r0 = (tid * 2) >> 2, c0 = ((tid * 2) & 3) * 4;
    const int r1 = (tid * 2 + 1) >> 2, c1 = ((tid * 2 + 1) & 3) * 4;

    unsigned long long acc2[8][4];
#pragma unroll
    for (int i = 0; i < 8; i++)
#pragma unroll
        for (int j = 0; j < 4; j++) acc2[i][j] = 0ull;

    // Prologue: load k-slice 0 into buffer 0.
    float4 va0 = *reinterpret_cast<const float4*>(Ab + (size_t)r0 * K + c0);
    float4 va1 = *reinterpret_cast<const float4*>(Ab + (size_t)r1 * K + c1);
    float4 vb0 = *reinterpret_cast<const float4*>(Bb + (size_t)r0 * K + c0);
    float4 vb1 = *reinterpret_cast<const float4*>(Bb + (size_t)r1 * K + c1);
    As[0][c0 + 0][r0] = va0.x; As[0][c0 + 1][r0] = va0.y; As[0][c0 + 2][r0] = va0.z; As[0][c0 + 3][r0] = va0.w;
    As[0][c1 + 0][r1] = va1.x; As[0][c1 + 1][r1] = va1.y; As[0][c1 + 2][r1] = va1.z; As[0][c1 + 3][r1] = va1.w;
    Bs[0][c0 + 0][r0] = vb0.x; Bs[0][c0 + 1][r0] = vb0.y; Bs[0][c0 + 2][r0] = vb0.z; Bs[0][c0 + 3][r0] = vb0.w;
    Bs[0][c1 + 0][r1] = vb1.x; Bs[0][c1 + 1][r1] = vb1.y; Bs[0][c1 + 2][r1] = vb1.z; Bs[0][c1 + 3][r1] = vb1.w;
    __syncthreads();

    int buf = 0;
    for (int k0 = 0; k0 < K; k0 += 16) {
        const bool more = (k0 + 16 < K);
        // Prefetch next k-slice into registers (hides DRAM/L2 under compute).
        if (more) {
            va0 = *reinterpret_cast<const float4*>(Ab + (size_t)r0 * K + k0 + 16 + c0);
            va1 = *reinterpret_cast<const float4*>(Ab + (size_t)r1 * K + k0 + 16 + c1);
            vb0 = *reinterpret_cast<const float4*>(Bb + (size_t)r0 * K + k0 + 16 + c0);
            vb1 = *reinterpret_cast<const float4*>(Bb + (size_t)r1 * K + k0 + 16 + c1);
        }
#pragma unroll
        for (int kk = 0; kk < 16; kk++) {
            float4 a0 = *reinterpret_cast<const float4*>(&As[buf][kk][ty * 8]);
            float4 a1 = *reinterpret_cast<const float4*>(&As[buf][kk][ty * 8 + 4]);
            float4 b0 = *reinterpret_cast<const float4*>(&Bs[buf][kk][tx * 8]);
            float4 b1 = *reinterpret_cast<const float4*>(&Bs[buf][kk][tx * 8 + 4]);
            unsigned long long rb2[4] = {pack2(b0.x, b0.y), pack2(b0.z, b0.w),
                                         pack2(b1.x, b1.y), pack2(b1.z, b1.w)};
            float ra[8] = {a0.x, a0.y, a0.z, a0.w, a1.x, a1.y, a1.z, a1.w};
#pragma unroll
            for (int i = 0; i < 8; i++) {
                unsigned long long ra2 = pack2(ra[i], ra[i]);
#pragma unroll
                for (int j = 0; j < 4; j++)
                    acc2[i][j] = fma2(ra2, rb2[j], acc2[i][j]);
            }
        }
        if (more) {
            int nb = buf ^ 1;
            As[nb][c0 + 0][r0] = va0.x; As[nb][c0 + 1][r0] = va0.y; As[nb][c0 + 2][r0] = va0.z; As[nb][c0 + 3][r0] = va0.w;
            As[nb][c1 + 0][r1] = va1.x; As[nb][c1 + 1][r1] = va1.y; As[nb][c1 + 2][r1] = va1.z; As[nb][c1 + 3][r1] = va1.w;
            Bs[nb][c0 + 0][r0] = vb0.x; Bs[nb][c0 + 1][r0] = vb0.y; Bs[nb][c0 + 2][r0] = vb0.z; Bs[nb][c0 + 3][r0] = vb0.w;
            Bs[nb][c1 + 0][r1] = vb1.x; Bs[nb][c1 + 1][r1] = vb1.y; Bs[nb][c1 + 2][r1] = vb1.z; Bs[nb][c1 + 3][r1] = vb1.w;
            __syncthreads();
        }
        buf ^= 1;
    }

    const int cb = blockIdx.x * 128 + tx * 8;
    float bb[8];
#pragma unroll
    for (int j = 0; j < 8; j++) bb[j] = bias[cb + j];
#pragma unroll
    for (int i = 0; i < 8; i++) {
        float* Cp = C + (size_t)(blockIdx.y * 128 + ty * 8 + i) * RTOT + cb;
#pragma unroll
        for (int j = 0; j < 4; j++) {
            float2 f = unpack2(acc2[i][j]);
            Cp[2 * j]     = f.x + bb[2 * j];
            Cp[2 * j + 1] = f.y + bb[2 * j + 1];
        }
    }
}

// ---------------- sequential GRU pass (direction-split, REDG barrier) ---------
// 128 CTAs: even CTAs = dir 0, odd CTAs = dir 1; each group of 64 CTAs syncs
// only among itself. One warp per GRU unit; w_hh register-resident as packed
// f32x2. Arrival: red.relaxed on a monotone counter. Poll: WARP 0 ONLY (all
// lanes load the same word -> one L2 request per warp per iteration); other
// warps wait at bar.sync.
__global__ __launch_bounds__(NTHR) void gru_pass(
    const float* __restrict__ Whh,   // [2, 3H, H] flat
    const float* __restrict__ bhh,   // [2, 3H] flat
    int layer)
{
    const float* Gi = layer ? g_Gi1 : g_Gi0;
    float* Hs = layer ? g_H1 : g_H0;

    const int d = blockIdx.x & 1;            // direction
    const int g = blockIdx.x >> 1;           // group-local CTA id (0..63)
    unsigned* cnt = &g_cnt[layer][d];

    __shared__ float h_sh[HDIM];             // own direction's hidden vector
    const int warp = threadIdx.x >> 5;
    const int lane = threadIdx.x & 31;
    const int i = g * NWARP + warp;          // 0..767 (hidden index within dir)
    const int u = d * HDIM + i;              // global unit index

    // Load this unit's w_hh rows (r,z,n) into registers as packed f32x2.
    unsigned long long wr[12], wz[12], wn[12];
    {
        const float* base = Whh + (size_t)d * G3 * HDIM;
        const unsigned long long* r64 = reinterpret_cast<const unsigned long long*>(base + (size_t)i * HDIM);
        const unsigned long long* z64 = reinterpret_cast<const unsigned long long*>(base + (size_t)(HDIM + i) * HDIM);
        const unsigned long long* n64 = reinterpret_cast<const unsigned long long*>(base + (size_t)(2 * HDIM + i) * HDIM);
#pragma unroll
        for (int m = 0; m < 12; m++) {
            int p = lane + 32 * m;
            wr[m] = r64[p]; wz[m] = z64[p]; wn[m] = n64[p];
        }
    }
    const float br = bhh[d * G3 + i];
    const float bz = bhh[d * G3 + HDIM + i];
    const float bn = bhh[d * G3 + 2 * HDIM + i];

    // Stage h row 0 (seeded by init_kernel; kernel-boundary sync makes it visible).
    {
        const float2* src = reinterpret_cast<const float2*>(Hs + d * HDIM);
        reinterpret_cast<float2*>(h_sh)[threadIdx.x] = __ldcg(src + threadIdx.x);
    }
    __syncthreads();

    float hprev = h_sh[i];                   // only lane 0's copy is used

    // Prefetch Gi gates for step 0.
    float gr = 0.f, gz = 0.f, gn = 0.f;
    if (lane == 0) {
        const float* gp = Gi + d * G3 + i;
        gr = __ldg(gp); gz = __ldg(gp + HDIM); gn = __ldg(gp + 2 * HDIM);
    }

    for (int t = 0; t < T_STEPS; t++) {
        // Packed h2h matvec from shared memory.
        const unsigned long long* h64 = reinterpret_cast<const unsigned long long*>(h_sh);
        unsigned long long ar = 0ull, az = 0ull, an = 0ull;
#pragma unroll
        for (int m = 0; m < 12; m++) {
            unsigned long long hv = h64[lane + 32 * m];
            ar = fma2(wr[m], hv, ar);
            az = fma2(wz[m], hv, az);
            an = fma2(wn[m], hv, an);
        }
        float2 fr = unpack2(ar), fz = unpack2(az), fn = unpack2(an);
        float sr = fr.x + fr.y, sz = fz.x + fz.y, sn = fn.x + fn.y;
#pragma unroll
        for (int off = 16; off > 0; off >>= 1) {
            sr += __shfl_down_sync(0xffffffffu, sr, off);
            sz += __shfl_down_sync(0xffffffffu, sz, off);
            sn += __shfl_down_sync(0xffffffffu, sn, off);
        }

        // Prefetch next step's Gi gates (~full step of latency to cover DRAM).
        float gr_n = 0.f, gz_n = 0.f, gn_n = 0.f;
        if (lane == 0 && t + 1 < T_STEPS) {
            const float* gp = Gi + (size_t)(t + 1) * RTOT + d * G3 + i;
            gr_n = __ldg(gp); gz_n = __ldg(gp + HDIM); gn_n = __ldg(gp + 2 * HDIM);
        }

        if (lane == 0) {
            float r = 1.f / (1.f + __expf(-(gr + sr + br)));
            float z = 1.f / (1.f + __expf(-(gz + sz + bz)));
            float n = tanhf(gn + r * (sn + bn));
            float hnew = (1.f - z) * n + z * hprev;
            hprev = hnew;
            __stcg(&Hs[(size_t)(t + 1) * DH2 + u], hnew);
        }
        gr = gr_n; gz = gz_n; gn = gn_n;

        __syncthreads();                       // all 12 warps' h stores issued
        if (threadIdx.x == 0) {
            __threadfence();                   // publish CTA's stores
            asm volatile("red.relaxed.gpu.global.add.u32 [%0],1;"
                         :: "l"(cnt) : "memory");
        }

        // WARP 0 ONLY polls the monotone counter; one broadcast request/iter.
        if (warp == 0) {
            unsigned tgt = (unsigned)(t + 1) * GCTA;
            unsigned v;
            do {
                asm volatile("ld.acquire.gpu.global.u32 %0,[%1];" : "=r"(v) : "l"(cnt));
            } while (v < tgt);
        }
        __syncthreads();                       // release the other 11 warps

        // Stage h row t+1 (own direction only: 3 KB).
        const float2* src = reinterpret_cast<const float2*>(Hs + (size_t)(t + 1) * DH2 + d * HDIM);
        reinterpret_cast<float2*>(h_sh)[threadIdx.x] = __ldcg(src + threadIdx.x);
        __syncthreads();
    }
}

// ---------------- final FC + sigmoid ------------------------------------------
__global__ void fc_kernel(const float* __restrict__ fcw,
                          const float* __restrict__ fcb,
                          float* __restrict__ out)
{
    int gw = (blockIdx.x * blockDim.x + threadIdx.x) >> 5;   // output index
    int lane = threadIdx.x & 31;
    if (gw >= 256) return;
    const float* h = g_H1 + (size_t)T_STEPS * DH2;
    float acc = 0.f;
    for (int k = lane; k < DH2; k += 32)
        acc += fcw[(size_t)gw * DH2 + k] * h[k];
#pragma unroll
    for (int off = 16; off > 0; off >>= 1)
        acc += __shfl_down_sync(0xffffffffu, acc, off);
    if (lane == 0)
        out[gw] = 1.f / (1.f + __expf(-(acc + fcb[gw])));
}

// ---------------- launch ------------------------------------------------------
extern "C" void kernel_launch(void* const* d_in, const int* in_sizes, int n_in,
                              void* d_out, int out_size)
{
    const float* x     = (const float*)d_in[0];
    const float* h0    = (const float*)d_in[1];
    const float* w_ih0 = (const float*)d_in[2];
    const float* w_hh0 = (const float*)d_in[3];
    const float* b_ih0 = (const float*)d_in[4];
    const float* b_hh0 = (const float*)d_in[5];
    const float* w_ih1 = (const float*)d_in[6];
    const float* w_hh1 = (const float*)d_in[7];
    const float* b_ih1 = (const float*)d_in[8];
    const float* b_hh1 = (const float*)d_in[9];
    const float* fc_w  = (const float*)d_in[10];
    const float* fc_b  = (const float*)d_in[11];
    float* out = (float*)d_out;

    (void)in_sizes; (void)n_in; (void)out_size;

    init_kernel<<<6, 256>>>(h0);

    // Gi0 = W_ih0 @ x + b_ih0
    sgemm_nt<<<dim3(RTOT / 128, T_STEPS / 128), 256>>>(x, w_ih0, b_ih0, D_INP, 0);

    // layer 0 sequential pass
    gru_pass<<<NCTA, NTHR>>>(w_hh0, b_hh0, 0);

    // Gi1 = W_ih1 @ h0_seq + b_ih1  (A=nullptr -> kernel uses g_H0+DH2)
    sgemm_nt<<<dim3(RTOT / 128, T_STEPS / 128), 256>>>(nullptr, w_ih1, b_ih1, DH2, 1);

    // layer 1 sequential pass
    gru_pass<<<NCTA, NTHR>>>(w_hh1, b_hh1, 1);

    // final FC + sigmoid
    fc_kernel<<<32, 256>>>(fc_w, fc_b, out);
}